// round 3
// baseline (speedup 1.0000x reference)
#include <cuda_runtime.h>
#include <math.h>

#define CN 64
#define CC 64
#define CT 300
#define CV 25
#define TVN 7500
#define ICN 16
#define EPSBN 1e-5f

static const int OFF_FA = 0;          // 23,040,000
static const int OFF_FB = 23040000;   // 23,040,000
static const int OFF_S  = 46080000;   // 120,000
static const int OFF_Z  = 46200000;   // 92,160,000  (later reused for yt)
static const int OFF_YG = 138360000;  // 30,720,000
// y2 reuses [0, 30.72M) (fa/fb dead after k_S)

__device__ float g_scratch[169080000];
__device__ float g_partsum[1024];
__device__ float g_partss[1024];
__device__ float g_bnA[64];
__device__ float g_bnB[64];

// ---------------------------------------------------------------------------
// K1: fa/fb 1x1 convs: GEMM 96rows x 64c x 7500cols per n
// ---------------------------------------------------------------------------
__global__ __launch_bounds__(192) void k_fafb(
    const float* __restrict__ x,
    const float* __restrict__ Wa, const float* __restrict__ ba,
    const float* __restrict__ Wb, const float* __restrict__ bb,
    float* __restrict__ fa, float* __restrict__ fb) {
  __shared__ float WS[96 * 65];
  __shared__ float xs[64 * 64];
  int n = blockIdx.y, c0 = blockIdx.x * 64;
  int tid = threadIdx.x;
  for (int m = tid; m < 96 * 64; m += 192) {
    int row = m >> 6, c = m & 63;
    WS[row * 65 + c] = (row < 48) ? Wa[row * 64 + c] : Wb[(row - 48) * 64 + c];
  }
  const float* xp = x + n * (CC * TVN);
  for (int m = tid; m < 64 * 64; m += 192) {
    int c = m >> 6, col = m & 63;
    int g = c0 + col;
    xs[m] = (g < TVN) ? xp[c * TVN + g] : 0.f;
  }
  __syncthreads();
  int ty = tid >> 4, tx = tid & 15;
  float acc[8][4];
#pragma unroll
  for (int r = 0; r < 8; r++)
#pragma unroll
    for (int j = 0; j < 4; j++) acc[r][j] = 0.f;
  for (int c = 0; c < 64; c++) {
    float wr[8], xr[4];
#pragma unroll
    for (int r = 0; r < 8; r++) wr[r] = WS[(ty * 8 + r) * 65 + c];
#pragma unroll
    for (int j = 0; j < 4; j++) xr[j] = xs[c * 64 + tx + 16 * j];
#pragma unroll
    for (int r = 0; r < 8; r++)
#pragma unroll
      for (int j = 0; j < 4; j++) acc[r][j] += wr[r] * xr[j];
  }
#pragma unroll
  for (int r = 0; r < 8; r++) {
    int row = ty * 8 + r;
    int rr = (row < 48) ? row : row - 48;
    float* outp = (row < 48) ? fa : fb;
    float bias = (row < 48) ? ba[rr] : bb[rr];
    int k = rr >> 4, i = rr & 15;
    int base = (k * CN + n) * (ICN * TVN) + i * TVN;
#pragma unroll
    for (int j = 0; j < 4; j++) {
      int col = c0 + tx + 16 * j;
      if (col < TVN) outp[base + col] = acc[r][j] + bias;
    }
  }
}

// ---------------------------------------------------------------------------
// K2: S[k,n,v,w] = (1/4800) sum_{i,t} fa*fb; softmax over v; + (adj+PA)
// one block per (k,n); 25 tiles of 5x5 outputs x 8-way e-split
// ---------------------------------------------------------------------------
__global__ __launch_bounds__(224) void k_S(
    const float* __restrict__ adj, const float* __restrict__ PA,
    const float* __restrict__ fa, const float* __restrict__ fb,
    float* __restrict__ Sout) {
  int k = blockIdx.x, n = blockIdx.y;
  __shared__ float sfa[1600], sfb[1600];
  __shared__ float sP[8 * 625];
  __shared__ float sS[625];
  __shared__ float smx[25], sinv[25];
  const float* fap = fa + (k * CN + n) * (ICN * TVN);
  const float* fbp = fb + (k * CN + n) * (ICN * TVN);
  int tid = threadIdx.x;
  float acc[25];
#pragma unroll
  for (int q = 0; q < 25; q++) acc[q] = 0.f;
  int tile = tid % 25, es = tid / 25;
  int vt = (tile / 5) * 5, wt = (tile % 5) * 5;
  for (int ch = 0; ch < 75; ch++) {
    __syncthreads();
    int d0 = ch * 64;
    for (int m = tid; m < 1600; m += 224) {
      int e = m / 25, vv = m - e * 25;
      int d = d0 + e;
      int i = d / 300, t = d - i * 300;
      int addr = i * TVN + t * 25 + vv;
      sfa[m] = fap[addr];
      sfb[m] = fbp[addr];
    }
    __syncthreads();
    if (tid < 200) {
#pragma unroll
      for (int ee = 0; ee < 8; ee++) {
        int e = es * 8 + ee;
        float av[5], bv[5];
#pragma unroll
        for (int q = 0; q < 5; q++) { av[q] = sfa[e * 25 + vt + q]; bv[q] = sfb[e * 25 + wt + q]; }
#pragma unroll
        for (int a2 = 0; a2 < 5; a2++)
#pragma unroll
          for (int b2 = 0; b2 < 5; b2++) acc[a2 * 5 + b2] += av[a2] * bv[b2];
      }
    }
  }
  __syncthreads();
  if (tid < 200) {
#pragma unroll
    for (int a2 = 0; a2 < 5; a2++)
#pragma unroll
      for (int b2 = 0; b2 < 5; b2++)
        sP[es * 625 + (vt + a2) * 25 + (wt + b2)] = acc[a2 * 5 + b2];
  }
  __syncthreads();
  for (int m = tid; m < 625; m += 224) {
    float s = 0.f;
#pragma unroll
    for (int e = 0; e < 8; e++) s += sP[e * 625 + m];
    sS[m] = s * (1.0f / 4800.0f);
  }
  __syncthreads();
  if (tid < 25) {  // tid = w; softmax over v (axis -2)
    float mx = -1e30f;
    for (int v = 0; v < 25; v++) mx = fmaxf(mx, sS[v * 25 + tid]);
    float sm = 0.f;
    for (int v = 0; v < 25; v++) sm += expf(sS[v * 25 + tid] - mx);
    smx[tid] = mx;
    sinv[tid] = 1.f / sm;
  }
  __syncthreads();
  float* so = Sout + (k * CN + n) * 625;
  for (int m = tid; m < 625; m += 224) {
    int w = m % 25;
    so[m] = expf(sS[m] - smx[w]) * sinv[w] + adj[k * 625 + m] + PA[k * 625 + m];
  }
}

// ---------------------------------------------------------------------------
// K3: Z[k,n,c,t,w] = sum_v x[n,c,t,v] * S[k,n,v,w]
// ---------------------------------------------------------------------------
__global__ __launch_bounds__(256) void k_Z(
    const float* __restrict__ x, const float* __restrict__ Sbuf,
    float* __restrict__ Z) {
  int n = blockIdx.y, t0 = blockIdx.x * 6;  // 50*6 = 300
  __shared__ float Ss[1875];
  __shared__ float xs[64 * 150];
  int tid = threadIdx.x;
  for (int m = tid; m < 1875; m += 256) {
    int k = m / 625;
    Ss[m] = Sbuf[(k * CN + n) * 625 + (m - k * 625)];
  }
  const float* xp = x + n * (CC * TVN) + t0 * 25;
  for (int m = tid; m < 64 * 150; m += 256) {
    int c = m / 150, col = m - c * 150;
    xs[m] = xp[c * TVN + col];
  }
  __syncthreads();
  // tasks: k(3) x cgroup(8) x tt(6) x wtile(5) = 720
  for (int tsk = tid; tsk < 720; tsk += 256) {
    int k = tsk / 240, r = tsk - k * 240;
    int cg = r / 30;
    int r2 = r - cg * 30;
    int tt = r2 / 5, wt = r2 - tt * 5;
    int cb = cg * 8, w0 = wt * 5;
    const float* sp = Ss + k * 625;
    float acc[8][5];
#pragma unroll
    for (int a2 = 0; a2 < 8; a2++)
#pragma unroll
      for (int b2 = 0; b2 < 5; b2++) acc[a2][b2] = 0.f;
    for (int v = 0; v < 25; v++) {
      float xv[8], sv[5];
#pragma unroll
      for (int ci = 0; ci < 8; ci++) xv[ci] = xs[(cb + ci) * 150 + tt * 25 + v];
#pragma unroll
      for (int wi = 0; wi < 5; wi++) sv[wi] = sp[v * 25 + w0 + wi];
#pragma unroll
      for (int ci = 0; ci < 8; ci++)
#pragma unroll
        for (int wi = 0; wi < 5; wi++) acc[ci][wi] += xv[ci] * sv[wi];
    }
#pragma unroll
    for (int ci = 0; ci < 8; ci++) {
      int base = ((k * CN + n) * CC + cb + ci) * TVN + (t0 + tt) * 25 + w0;
#pragma unroll
      for (int wi = 0; wi < 5; wi++) Z[base + wi] = acc[ci][wi];
    }
  }
}

// ---------------------------------------------------------------------------
// K4: y1[n,o,col] = sum_{kc=0..191} Wd2[kc][o] * Z[kc][col]   (per n)
// ---------------------------------------------------------------------------
__global__ __launch_bounds__(256) void k_yg(
    const float* __restrict__ Z, const float* __restrict__ Wd,
    float* __restrict__ y1) {
  __shared__ float Ws[32 * 64];
  __shared__ float Zs[32 * 64];
  int n = blockIdx.y, col0 = blockIdx.x * 64;
  int tid = threadIdx.x;
  int ty = tid >> 4, tx = tid & 15;
  float acc[4][4];
#pragma unroll
  for (int r = 0; r < 4; r++)
#pragma unroll
    for (int j = 0; j < 4; j++) acc[r][j] = 0.f;
  for (int ch = 0; ch < 6; ch++) {
    __syncthreads();
    int kc0 = ch * 32;
    for (int m = tid; m < 2048; m += 256) {
      int r = m >> 6, o = m & 63;
      int kc = kc0 + r, k = kc >> 6, c = kc & 63;
      Ws[m] = Wd[k * 4096 + o * 64 + c];
      int col = o;  // reuse decomposition for Zs
      int gcol = col0 + col;
      Zs[m] = (gcol < TVN) ? Z[((k * CN + n) * CC + c) * TVN + gcol] : 0.f;
    }
    __syncthreads();
    for (int r = 0; r < 32; r++) {
      float wr[4], xr[4];
#pragma unroll
      for (int ri = 0; ri < 4; ri++) wr[ri] = Ws[r * 64 + ty * 4 + ri];
#pragma unroll
      for (int j = 0; j < 4; j++) xr[j] = Zs[r * 64 + tx + 16 * j];
#pragma unroll
      for (int ri = 0; ri < 4; ri++)
#pragma unroll
        for (int j = 0; j < 4; j++) acc[ri][j] += wr[ri] * xr[j];
    }
  }
#pragma unroll
  for (int ri = 0; ri < 4; ri++) {
    int o = ty * 4 + ri;
    int base = (n * CC + o) * TVN;
#pragma unroll
    for (int j = 0; j < 4; j++) {
      int col = col0 + tx + 16 * j;
      if (col < TVN) y1[base + col] = acc[ri][j];
    }
  }
}

// ---------------------------------------------------------------------------
// K5: per-channel partial sums for BN (grid 64 x 16)
// ---------------------------------------------------------------------------
__global__ __launch_bounds__(256) void k_stats(const float4* __restrict__ in) {
  int o = blockIdx.x, s = blockIdx.y;
  int tid = threadIdx.x;
  float sum = 0.f, ss = 0.f;
  for (int m = tid; m < 7500; m += 256) {
    int nn = s * 4 + m / 1875;
    int j4 = m - (m / 1875) * 1875;
    float4 v = in[(nn * CC + o) * 1875 + j4];
    sum += v.x + v.y + v.z + v.w;
    ss += v.x * v.x + v.y * v.y + v.z * v.z + v.w * v.w;
  }
  __shared__ float s1[8], s2[8];
#pragma unroll
  for (int off = 16; off > 0; off >>= 1) {
    sum += __shfl_down_sync(0xffffffffu, sum, off);
    ss += __shfl_down_sync(0xffffffffu, ss, off);
  }
  if ((tid & 31) == 0) { s1[tid >> 5] = sum; s2[tid >> 5] = ss; }
  __syncthreads();
  if (tid == 0) {
    float a = 0.f, b = 0.f;
#pragma unroll
    for (int w = 0; w < 8; w++) { a += s1[w]; b += s2[w]; }
    g_partsum[o * 16 + s] = a;
    g_partss[o * 16 + s] = b;
  }
}

__global__ void k_bnfinal(const float* __restrict__ gamma, const float* __restrict__ beta) {
  int o = threadIdx.x;
  float a = 0.f, b = 0.f;
#pragma unroll
  for (int s = 0; s < 16; s++) { a += g_partsum[o * 16 + s]; b += g_partss[o * 16 + s]; }
  float inv = 1.0f / 480000.0f;
  float mu = a * inv;
  float var = b * inv - mu * mu;
  float A = gamma[o] * rsqrtf(var + EPSBN);
  g_bnA[o] = A;
  g_bnB[o] = beta[o] - mu * A;
}

// ---------------------------------------------------------------------------
// K6: out = relu(A[o]*in + B[o] + x)
// ---------------------------------------------------------------------------
__global__ __launch_bounds__(256) void k_addrelu(
    const float4* __restrict__ in, const float4* __restrict__ x,
    float4* __restrict__ out) {
  int i = blockIdx.x * 256 + threadIdx.x;  // 7,680,000 float4s
  int o = (i / 1875) & 63;
  float A = g_bnA[o], B = g_bnB[o];
  float4 v = in[i], xx = x[i], r;
  r.x = fmaxf(A * v.x + B + xx.x, 0.f);
  r.y = fmaxf(A * v.y + B + xx.y, 0.f);
  r.z = fmaxf(A * v.z + B + xx.z, 0.f);
  r.w = fmaxf(A * v.w + B + xx.w, 0.f);
  out[i] = r;
}

// ---------------------------------------------------------------------------
// K7: temporal conv KT=9 pad 4: 9 shifted 64x64 GEMMs over haloed col tile
// ---------------------------------------------------------------------------
__global__ __launch_bounds__(256) void k_tcn(
    const float* __restrict__ y2, const float* __restrict__ Wt,
    float* __restrict__ yt) {
  __shared__ float y2cs[8 * 264];
  __shared__ float Ws[8 * 9 * 64];
  int n = blockIdx.y, col0 = blockIdx.x * 64;
  int tid = threadIdx.x;
  int ty = tid >> 4, tx = tid & 15;
  int o0 = ty * 4;
  float acc[4][4];
#pragma unroll
  for (int r = 0; r < 4; r++)
#pragma unroll
    for (int j = 0; j < 4; j++) acc[r][j] = 0.f;
  for (int cc = 0; cc < 8; cc++) {
    __syncthreads();
    for (int m = tid; m < 2112; m += 256) {
      int c = m / 264, lc = m - c * 264;
      int cg = cc * 8 + c;
      int gc = col0 - 100 + lc;
      y2cs[m] = (gc >= 0 && gc < TVN) ? y2[(n * CC + cg) * TVN + gc] : 0.f;
    }
    for (int m = tid; m < 4608; m += 256) {
      int o = m & 63, cdt = m >> 6;
      Ws[m] = Wt[o * 576 + cc * 72 + cdt];
    }
    __syncthreads();
#pragma unroll
    for (int dt = 0; dt < 9; dt++) {
      int sh = dt * 25;
#pragma unroll
      for (int c = 0; c < 8; c++) {
        float wr[4], xr[4];
#pragma unroll
        for (int ri = 0; ri < 4; ri++) wr[ri] = Ws[(c * 9 + dt) * 64 + o0 + ri];
#pragma unroll
        for (int j = 0; j < 4; j++) xr[j] = y2cs[c * 264 + tx + 16 * j + sh];
#pragma unroll
        for (int ri = 0; ri < 4; ri++)
#pragma unroll
          for (int j = 0; j < 4; j++) acc[ri][j] += wr[ri] * xr[j];
      }
    }
  }
#pragma unroll
  for (int ri = 0; ri < 4; ri++) {
    int base = (n * CC + o0 + ri) * TVN;
#pragma unroll
    for (int j = 0; j < 4; j++) {
      int col = col0 + tx + 16 * j;
      if (col < TVN) yt[base + col] = acc[ri][j];
    }
  }
}

__global__ void k_copyadj(const float* __restrict__ adj, float* __restrict__ out) {
  int i = blockIdx.x * 256 + threadIdx.x;
  if (i < 1875) out[30720000 + i] = adj[i];
}

extern "C" void kernel_launch(void* const* d_in, const int* in_sizes, int n_in,
                              void* d_out, int out_size) {
  const float* x   = (const float*)d_in[0];
  const float* adj = (const float*)d_in[1];
  const float* PA  = (const float*)d_in[2];
  const float* Wa  = (const float*)d_in[3];
  const float* ba  = (const float*)d_in[4];
  const float* Wb  = (const float*)d_in[5];
  const float* bb  = (const float*)d_in[6];
  const float* Wd  = (const float*)d_in[7];
  // d_in[8] = bd (cancels through BN), d_in[9]=g1, d_in[10]=b1
  const float* g1  = (const float*)d_in[9];
  const float* b1  = (const float*)d_in[10];
  const float* Wt  = (const float*)d_in[11];
  // d_in[12] = bt (cancels through BN)
  const float* g2  = (const float*)d_in[13];
  const float* b2  = (const float*)d_in[14];
  float* out = (float*)d_out;

  float* sc = nullptr;
  cudaGetSymbolAddress((void**)&sc, g_scratch);

  dim3 gGemm(118, 64);
  k_fafb<<<gGemm, 192>>>(x, Wa, ba, Wb, bb, sc + OFF_FA, sc + OFF_FB);
  dim3 gS(3, 64);
  k_S<<<gS, 224>>>(adj, PA, sc + OFF_FA, sc + OFF_FB, sc + OFF_S);
  dim3 gZ(50, 64);
  k_Z<<<gZ, 256>>>(x, sc + OFF_S, sc + OFF_Z);
  k_yg<<<gGemm, 256>>>(sc + OFF_Z, Wd, sc + OFF_YG);
  dim3 gSt(64, 16);
  k_stats<<<gSt, 256>>>((const float4*)(sc + OFF_YG));
  k_bnfinal<<<1, 64>>>(g1, b1);
  k_addrelu<<<30000, 256>>>((const float4*)(sc + OFF_YG), (const float4*)x,
                            (float4*)(sc + 0));
  k_tcn<<<gGemm, 256>>>(sc + 0, Wt, sc + OFF_Z);  // yt reuses Z region
  k_stats<<<gSt, 256>>>((const float4*)(sc + OFF_Z));
  k_bnfinal<<<1, 64>>>(g2, b2);
  k_addrelu<<<30000, 256>>>((const float4*)(sc + OFF_Z), (const float4*)x,
                            (float4*)out);
  if (out_size > 30720000) k_copyadj<<<8, 256>>>(adj, out);
}